// round 12
// baseline (speedup 1.0000x reference)
#include <cuda_runtime.h>
#include <cuda_bf16.h>
#include <math.h>
#include <stdint.h>

// Problem constants
#define NQ 512
#define NC 65536
#define D  768
#define PD 64          // packed projection dim: e[0:32) h[32:48) s[48:64)

typedef unsigned long long u64;

// packed-fp32 helpers (proj kernel)
__device__ __forceinline__ u64 pack2(float v) {
    u64 r;
    asm("mov.b64 %0, {%1, %1};" : "=l"(r) : "f"(v));
    return r;
}
__device__ __forceinline__ void fma2(u64& d, u64 a, u64 b) {
    asm("fma.rn.f32x2 %0, %1, %2, %0;" : "+l"(d) : "l"(a), "l"(b));
}
__device__ __forceinline__ void unpack2(float& lo, float& hi, u64 v) {
    asm("mov.b64 {%0, %1}, %2;" : "=f"(lo), "=f"(hi) : "l"(v));
}

// bf16 mma.sync (sm_80 PTX — legal on baseline compute_103)
__device__ __forceinline__ void mma_bf16(float* d, const uint32_t* a, const uint32_t* b) {
    asm volatile(
        "mma.sync.aligned.m16n8k16.row.col.f32.bf16.bf16.f32 "
        "{%0,%1,%2,%3},{%4,%5,%6,%7},{%8,%9},{%0,%1,%2,%3};"
        : "+f"(d[0]), "+f"(d[1]), "+f"(d[2]), "+f"(d[3])
        : "r"(a[0]), "r"(a[1]), "r"(a[2]), "r"(a[3]), "r"(b[0]), "r"(b[1]));
}

// fast acos: A&S 4.4.46-style 8-coeff, abs err ~2e-8
__device__ __forceinline__ float facos(float x) {
    float ax = fabsf(x);
    float p = fmaf(ax, -0.0012624911f, 0.0066700901f);
    p = fmaf(p, ax, -0.0170881256f);
    p = fmaf(p, ax,  0.0308918810f);
    p = fmaf(p, ax, -0.0501743046f);
    p = fmaf(p, ax,  0.0889789874f);
    p = fmaf(p, ax, -0.2145988016f);
    p = fmaf(p, ax,  1.5707963050f);
    float r = sqrtf(1.0f - ax) * p;
    return (x >= 0.0f) ? r : (3.14159265358979f - r);
}

// Scratch: projections stored as exact bf16 hi/lo splits
__device__ __nv_bfloat16 g_chi[(size_t)NC * PD];
__device__ __nv_bfloat16 g_clo[(size_t)NC * PD];
__device__ __nv_bfloat16 g_qhi[(size_t)NQ * PD];
__device__ __nv_bfloat16 g_qlo[(size_t)NQ * PD];
__device__ float g_cyn[NC];
__device__ float g_qxn[NQ];
__device__ float g_qw[(size_t)NQ * 3];

// ---------------------------------------------------------------------------
// Kernel 1: weight MLP (unchanged, passing since R5)
// ---------------------------------------------------------------------------
__global__ __launch_bounds__(256) void mlp_kernel(
    const float* __restrict__ xq,
    const float* __restrict__ W1, const float* __restrict__ b1,
    const float* __restrict__ W2, const float* __restrict__ b2)
{
    __shared__ float xs[D];
    __shared__ float hid[32];

    const int q    = blockIdx.x;
    const int tid  = threadIdx.x;
    const int warp = tid >> 5, lane = tid & 31;

    const float4* xrow4 = (const float4*)(xq + (size_t)q * D);
    if (tid < D / 4) ((float4*)xs)[tid] = xrow4[tid];
    __syncthreads();

    float acc0 = 0.f, acc1 = 0.f, acc2 = 0.f, acc3 = 0.f;
    const float* w0  = W1 + (size_t)(warp * 4 + 0) * D;
    const float* w1r = W1 + (size_t)(warp * 4 + 1) * D;
    const float* w2r = W1 + (size_t)(warp * 4 + 2) * D;
    const float* w3r = W1 + (size_t)(warp * 4 + 3) * D;
    #pragma unroll 4
    for (int k = lane; k < D; k += 32) {
        float xv = xs[k];
        acc0 = fmaf(w0[k],  xv, acc0);
        acc1 = fmaf(w1r[k], xv, acc1);
        acc2 = fmaf(w2r[k], xv, acc2);
        acc3 = fmaf(w3r[k], xv, acc3);
    }
    #pragma unroll
    for (int o = 16; o; o >>= 1) {
        acc0 += __shfl_xor_sync(0xffffffffu, acc0, o);
        acc1 += __shfl_xor_sync(0xffffffffu, acc1, o);
        acc2 += __shfl_xor_sync(0xffffffffu, acc2, o);
        acc3 += __shfl_xor_sync(0xffffffffu, acc3, o);
    }
    if (lane == 0) {
        hid[warp * 4 + 0] = fmaxf(acc0 + b1[warp * 4 + 0], 0.0f);
        hid[warp * 4 + 1] = fmaxf(acc1 + b1[warp * 4 + 1], 0.0f);
        hid[warp * 4 + 2] = fmaxf(acc2 + b1[warp * 4 + 2], 0.0f);
        hid[warp * 4 + 3] = fmaxf(acc3 + b1[warp * 4 + 3], 0.0f);
    }
    __syncthreads();

    if (warp == 0) {
        float h = hid[lane];
        #pragma unroll
        for (int i = 0; i < 3; i++) {
            float p = h * W2[i * 32 + lane];
            #pragma unroll
            for (int o = 16; o; o >>= 1) p += __shfl_xor_sync(0xffffffffu, p, o);
            if (lane == 0) {
                float z  = p + b2[i];
                float sp = fmaxf(z, 0.0f) + log1pf(expf(-fabsf(z)));
                g_qw[(size_t)q * 3 + i] = sp;
            }
        }
    }
}

// ---------------------------------------------------------------------------
// Kernel 2: projection GEMM (R11 mainloop) + epilogue writing bf16 hi/lo.
// ---------------------------------------------------------------------------
#define BK 32
#define ROWPAD 132
#define NCB128 (NC / 128)
#define NQB128 (NQ / 128)

#define XS_OFF  0
#define WS_OFF  (BK * ROWPAD)
#define OB_SZ   (128 * 68)
#define SRAW_FLOATS (OB_SZ > (BK*ROWPAD + BK*68) ? OB_SZ : (BK*ROWPAD + BK*68))

__global__ __launch_bounds__(256) void proj_kernel(
    const float* __restrict__ xc,
    const float* __restrict__ xq,
    const float* __restrict__ We, const float* __restrict__ be,
    const float* __restrict__ Wh, const float* __restrict__ bh,
    const float* __restrict__ Ws, const float* __restrict__ bs,
    const float* __restrict__ scale_h_p)
{
    __shared__ __align__(16) float sraw[SRAW_FLOATS];
    __shared__ float bias_s[64];

    float* xs  = sraw + XS_OFF;
    float* wsm = sraw + WS_OFF;
    float* ob  = sraw;

    const int tid = threadIdx.x;
    const int blk = blockIdx.x;
    const bool isQ  = (blk >= NCB128);
    const int  row0 = isQ ? (blk - NCB128) * 128 : blk * 128;
    const float* xsrc = isQ ? xq : xc;
    __nv_bfloat16* ghi = isQ ? g_qhi : g_chi;
    __nv_bfloat16* glo = isQ ? g_qlo : g_clo;
    float* gyn = isQ ? g_qxn : g_cyn;

    if (tid < 64) {
        float b;
        if (tid < 32)      b = be[tid];
        else if (tid < 48) b = bh[tid - 32];
        else               b = bs[tid - 48];
        bias_s[tid] = b;
    }

    const float* wrow_base[2];
    {
        int n0 = (tid + 0 * 256) >> 3;
        int n1 = (tid + 1 * 256) >> 3;
        wrow_base[0] = (n0 < 32) ? We + (size_t)n0 * D
                      : (n0 < 48) ? Wh + (size_t)(n0 - 32) * D
                                  : Ws + (size_t)(n0 - 48) * D;
        wrow_base[1] = (n1 < 32) ? We + (size_t)n1 * D
                      : (n1 < 48) ? Wh + (size_t)(n1 - 32) * D
                                  : Ws + (size_t)(n1 - 48) * D;
    }

    const int tr = (tid >> 4) * 8;
    const int tc = (tid & 15) * 4;

    u64 acc[8][2] = {};
    const float* xbase = xsrc + (size_t)row0 * D;

    for (int kk = 0; kk < D; kk += BK) {
        float4 xv[4], wv[2];
        #pragma unroll
        for (int i = 0; i < 4; i++) {
            int idx = tid + i * 256;
            int r   = idx >> 3;
            int k4  = (idx & 7) * 4;
            xv[i] = *(const float4*)(xbase + (size_t)r * D + kk + k4);
        }
        #pragma unroll
        for (int i = 0; i < 2; i++) {
            int idx = tid + i * 256;
            int k4  = (idx & 7) * 4;
            wv[i] = *(const float4*)(wrow_base[i] + kk + k4);
        }
        __syncthreads();
        #pragma unroll
        for (int i = 0; i < 4; i++) {
            int idx = tid + i * 256;
            int r   = idx >> 3;
            int k4  = (idx & 7) * 4;
            xs[(k4 + 0) * ROWPAD + r] = xv[i].x;
            xs[(k4 + 1) * ROWPAD + r] = xv[i].y;
            xs[(k4 + 2) * ROWPAD + r] = xv[i].z;
            xs[(k4 + 3) * ROWPAD + r] = xv[i].w;
        }
        #pragma unroll
        for (int i = 0; i < 2; i++) {
            int idx = tid + i * 256;
            int n   = idx >> 3;
            int k4  = (idx & 7) * 4;
            wsm[(k4 + 0) * 68 + n] = wv[i].x;
            wsm[(k4 + 1) * 68 + n] = wv[i].y;
            wsm[(k4 + 2) * 68 + n] = wv[i].z;
            wsm[(k4 + 3) * 68 + n] = wv[i].w;
        }
        __syncthreads();

        #pragma unroll
        for (int k = 0; k < BK; k++) {
            float4 a0 = *(const float4*)&xs[k * ROWPAD + tr];
            float4 a1 = *(const float4*)&xs[k * ROWPAD + tr + 4];
            ulonglong2 b = *(const ulonglong2*)&wsm[k * 68 + tc];
            u64 ap[8];
            ap[0] = pack2(a0.x); ap[1] = pack2(a0.y);
            ap[2] = pack2(a0.z); ap[3] = pack2(a0.w);
            ap[4] = pack2(a1.x); ap[5] = pack2(a1.y);
            ap[6] = pack2(a1.z); ap[7] = pack2(a1.w);
            #pragma unroll
            for (int i = 0; i < 8; i++) {
                fma2(acc[i][0], ap[i], b.x);
                fma2(acc[i][1], ap[i], b.y);
            }
        }
        __syncthreads();
    }

    #pragma unroll
    for (int i = 0; i < 8; i++) {
        float v0, v1, v2, v3;
        unpack2(v0, v1, acc[i][0]);
        unpack2(v2, v3, acc[i][1]);
        float4 w4 = {v0, v1, v2, v3};
        *(float4*)&ob[(tr + i) * 68 + tc] = w4;
    }
    __syncthreads();

    // epilogue: 128 rows x 4 parts; writes exact bf16 hi/lo splits
    const float sc = *scale_h_p;
    #pragma unroll
    for (int it = 0; it < 2; it++) {
        const int r    = (tid >> 2) + it * 64;
        const int part = tid & 3;
        const int cbase = part * 16;
        float vals[16];
        float ss = 0.0f;
        #pragma unroll
        for (int j = 0; j < 16; j++) {
            float v = ob[r * 68 + cbase + j] + bias_s[cbase + j];
            if (part == 2) v *= sc;
            vals[j] = v;
            ss += v * v;
        }
        float other = __shfl_xor_sync(0xffffffffu, ss, 1);
        float seg   = (part < 2) ? (ss + other) : ss;

        const int grow = row0 + r;
        float f;
        if (part == 2) {
            float n  = fmaxf(sqrtf(seg), 1e-15f);
            float ex = __expf(2.0f * n);
            float th = 1.0f - 2.0f / (ex + 1.0f);
            f = th / n;
            gyn[grow] = th * th;
        } else {
            f = rsqrtf(seg);
        }
        // split each scaled value into bf16 hi + lo, pack pairs, store 32B
        uint32_t hp[8], lp[8];
        #pragma unroll
        for (int j = 0; j < 8; j++) {
            float v0 = vals[2 * j]     * f;
            float v1 = vals[2 * j + 1] * f;
            __nv_bfloat16 h0 = __float2bfloat16(v0);
            __nv_bfloat16 h1 = __float2bfloat16(v1);
            __nv_bfloat16 l0 = __float2bfloat16(v0 - __bfloat162float(h0));
            __nv_bfloat16 l1 = __float2bfloat16(v1 - __bfloat162float(h1));
            hp[j] = (uint32_t)*(uint16_t*)&h0 | ((uint32_t)*(uint16_t*)&h1 << 16);
            lp[j] = (uint32_t)*(uint16_t*)&l0 | ((uint32_t)*(uint16_t*)&l1 << 16);
        }
        uint32_t* hdst = (uint32_t*)(ghi + (size_t)grow * PD + cbase);
        uint32_t* ldst = (uint32_t*)(glo + (size_t)grow * PD + cbase);
        *(uint4*)(hdst + 0) = make_uint4(hp[0], hp[1], hp[2], hp[3]);
        *(uint4*)(hdst + 4) = make_uint4(hp[4], hp[5], hp[6], hp[7]);
        *(uint4*)(ldst + 0) = make_uint4(lp[0], lp[1], lp[2], lp[3]);
        *(uint4*)(ldst + 4) = make_uint4(lp[4], lp[5], lp[6], lp[7]);
    }
}

// ---------------------------------------------------------------------------
// Kernel 3: pairwise via mma.sync bf16 (hi/lo split, 3 MMAs per dot).
// Block: 64q x 64c, 8 warps; warp tile 16q x 32c. K=64: e=k[0:32), h=[32:48),
// s=[48:64) -> k-chunks 0,1 / 2 / 3 into separate accumulators.
// ---------------------------------------------------------------------------
#define QPITCH 72   // bf16 row pitch: 144B = 36 words -> conflict-free frags

__global__ __launch_bounds__(256) void pairwise_kernel(float* __restrict__ out)
{
    __shared__ __align__(16) __nv_bfloat16 s_qhi[64][QPITCH];
    __shared__ __align__(16) __nv_bfloat16 s_qlo[64][QPITCH];
    __shared__ __align__(16) __nv_bfloat16 s_chi[64][QPITCH];
    __shared__ __align__(16) __nv_bfloat16 s_clo[64][QPITCH];
    __shared__ float sqxn[64];
    __shared__ float sqw[64][3];
    __shared__ float scyn[64];

    const int tid   = threadIdx.x;
    const int c0blk = blockIdx.x * 64;
    const int q0blk = blockIdx.y * 64;

    // load tiles: 64 rows x 128B per array, as uint4 (2 per thread per array)
    #pragma unroll
    for (int i = 0; i < 2; i++) {
        int idx = tid + i * 256;       // 0..511
        int r   = idx >> 3;            // 0..63
        int j   = idx & 7;             // 0..7 (16B units)
        const uint4* qh = (const uint4*)(g_qhi + (size_t)(q0blk + r) * PD);
        const uint4* ql = (const uint4*)(g_qlo + (size_t)(q0blk + r) * PD);
        const uint4* ch = (const uint4*)(g_chi + (size_t)(c0blk + r) * PD);
        const uint4* cl = (const uint4*)(g_clo + (size_t)(c0blk + r) * PD);
        *(uint4*)&s_qhi[r][j * 8] = qh[j];
        *(uint4*)&s_qlo[r][j * 8] = ql[j];
        *(uint4*)&s_chi[r][j * 8] = ch[j];
        *(uint4*)&s_clo[r][j * 8] = cl[j];
    }
    if (tid < 64) {
        sqxn[tid]   = g_qxn[q0blk + tid];
        scyn[tid]   = g_cyn[c0blk + tid];
        sqw[tid][0] = g_qw[(size_t)(q0blk + tid) * 3 + 0];
        sqw[tid][1] = g_qw[(size_t)(q0blk + tid) * 3 + 1];
        sqw[tid][2] = g_qw[(size_t)(q0blk + tid) * 3 + 2];
    }
    __syncthreads();

    const int warp = tid >> 5, lane = tid & 31;
    const int wq0 = (warp & 3) * 16;     // q base within block
    const int wc0 = (warp >> 2) * 32;    // c base within block
    const int g   = lane >> 2;           // 0..7
    const int tig = lane & 3;            // 0..3

    float De[4][4] = {}, Dh[4][4] = {}, Ds[4][4] = {};

    #pragma unroll
    for (int kc = 0; kc < 4; kc++) {
        const int k0 = kc * 16 + 2 * tig;
        const int k1 = k0 + 8;
        const int r0 = wq0 + g, r1 = r0 + 8;
        uint32_t ah[4], al[4];
        ah[0] = *(const uint32_t*)&s_qhi[r0][k0];
        ah[1] = *(const uint32_t*)&s_qhi[r1][k0];
        ah[2] = *(const uint32_t*)&s_qhi[r0][k1];
        ah[3] = *(const uint32_t*)&s_qhi[r1][k1];
        al[0] = *(const uint32_t*)&s_qlo[r0][k0];
        al[1] = *(const uint32_t*)&s_qlo[r1][k0];
        al[2] = *(const uint32_t*)&s_qlo[r0][k1];
        al[3] = *(const uint32_t*)&s_qlo[r1][k1];
        #pragma unroll
        for (int nc = 0; nc < 4; nc++) {
            const int n = wc0 + nc * 8 + g;
            uint32_t bh[2], bl[2];
            bh[0] = *(const uint32_t*)&s_chi[n][k0];
            bh[1] = *(const uint32_t*)&s_chi[n][k1];
            bl[0] = *(const uint32_t*)&s_clo[n][k0];
            bl[1] = *(const uint32_t*)&s_clo[n][k1];
            float* Dp = (kc < 2) ? De[nc] : (kc == 2 ? Dh[nc] : Ds[nc]);
            mma_bf16(Dp, ah, bh);
            mma_bf16(Dp, ah, bl);
            mma_bf16(Dp, al, bh);
        }
    }

    // epilogue: thread owns rows {wq0+g, wq0+g+8}, cols {2tig, 2tig+1} per nc
    const int qa = wq0 + g, qb = qa + 8;
    const float xna = sqxn[qa], xnb = sqxn[qb];
    const float w0a = sqw[qa][0], w1a = sqw[qa][1], w2a = sqw[qa][2];
    const float w0b = sqw[qb][0], w1b = sqw[qb][1], w2b = sqw[qb][2];

    #pragma unroll
    for (int nc = 0; nc < 4; nc++) {
        const int cb = wc0 + nc * 8 + 2 * tig;     // local col base
        const float yn0 = scyn[cb], yn1 = scyn[cb + 1];
        #pragma unroll
        for (int rs = 0; rs < 2; rs++) {
            const int   qrow = rs ? qb : qa;
            const float xn   = rs ? xnb : xna;
            const float w0   = rs ? w0b : w0a;
            const float w1   = rs ? w1b : w1a;
            const float w2   = rs ? w2b : w2a;
            const float beta = 1.0f - xn;
            float rv[2];
            #pragma unroll
            for (int cs = 0; cs < 2; cs++) {
                const float yn = cs ? yn1 : yn0;
                const float ev = De[nc][rs * 2 + cs];
                const float hv = Dh[nc][rs * 2 + cs];
                const float svv = Ds[nc][rs * 2 + cs];
                float de = 2.0f - 2.0f * ev;
                float dots = fminf(fmaxf(svv, -1.0f + 1e-7f), 1.0f - 1e-7f);
                float acs  = facos(dots);
                float ds   = acs * acs;
                float alpha = 1.0f - 2.0f * hv + yn;
                float nsq   = alpha*alpha*xn - 2.0f*alpha*beta*hv + beta*beta*yn;
                float den   = fmaxf(1.0f - 2.0f*hv + xn*yn, 1e-15f);
                float t     = __fdividef(sqrtf(fmaxf(nsq, 0.0f)), den);
                t = fminf(fmaxf(t, 0.0f), 1.0f - 1e-7f);
                float dd = __logf(__fdividef(1.0f + t, 1.0f - t));
                rv[cs] = -(w0 * de + w1 * dd * dd + w2 * ds);
            }
            float2 res = {rv[0], rv[1]};
            *(float2*)(out + (size_t)(q0blk + qrow) * NC + c0blk + cb) = res;
        }
    }
}

// ---------------------------------------------------------------------------
extern "C" void kernel_launch(void* const* d_in, const int* in_sizes, int n_in,
                              void* d_out, int out_size)
{
    const float* xq  = (const float*)d_in[0];
    const float* xc  = (const float*)d_in[1];
    const float* We  = (const float*)d_in[2];
    const float* be  = (const float*)d_in[3];
    const float* Wh  = (const float*)d_in[4];
    const float* bh  = (const float*)d_in[5];
    const float* Ws  = (const float*)d_in[6];
    const float* bs  = (const float*)d_in[7];
    const float* sh  = (const float*)d_in[8];
    const float* W1  = (const float*)d_in[9];
    const float* b1  = (const float*)d_in[10];
    const float* W2  = (const float*)d_in[11];
    const float* b2  = (const float*)d_in[12];
    float* out = (float*)d_out;

    mlp_kernel<<<NQ, 256>>>(xq, W1, b1, W2, b2);
    proj_kernel<<<NCB128 + NQB128, 256>>>(xc, xq, We, be, Wh, bh, Ws, bs, sh);
    pairwise_kernel<<<dim3(NC / 64, NQ / 64), 256>>>(out);
}

// round 14
// speedup vs baseline: 1.0720x; 1.0720x over previous
#include <cuda_runtime.h>
#include <math.h>
#include <stdint.h>

// Problem constants
#define NQ 512
#define NC 65536
#define D  768
#define PD 64          // packed projection dim: e[0:32) h[32:48) s[48:64)

typedef unsigned long long u64;

// packed-fp32 helpers (sm_103 f32x2 — 2x FFMA throughput, exact fp32)
__device__ __forceinline__ u64 pack2(float v) {
    u64 r;
    asm("mov.b64 %0, {%1, %1};" : "=l"(r) : "f"(v));
    return r;
}
__device__ __forceinline__ u64 packpair(float lo, float hi) {
    u64 r;
    asm("mov.b64 %0, {%1, %2};" : "=l"(r) : "f"(lo), "f"(hi));
    return r;
}
__device__ __forceinline__ void fma2(u64& d, u64 a, u64 b) {
    asm("fma.rn.f32x2 %0, %1, %2, %0;" : "+l"(d) : "l"(a), "l"(b));
}
__device__ __forceinline__ u64 fma2v(u64 a, u64 b, u64 c) {
    u64 r;
    asm("fma.rn.f32x2 %0, %1, %2, %3;" : "=l"(r) : "l"(a), "l"(b), "l"(c));
    return r;
}
__device__ __forceinline__ u64 mul2(u64 a, u64 b) {
    u64 r;
    asm("mul.rn.f32x2 %0, %1, %2;" : "=l"(r) : "l"(a), "l"(b));
    return r;
}
__device__ __forceinline__ void unpack2(float& lo, float& hi, u64 v) {
    asm("mov.b64 {%0, %1}, %2;" : "=f"(lo), "=f"(hi) : "l"(v));
}

// hyperbolic distance scalar core: dd = 2*atanh(min(sqrt(nsq)/den, 1-1e-7))
//   = ln((den+s)/(den-s)) with s clamped
__device__ __forceinline__ float hyp_dd(float nsq, float den) {
    den = fmaxf(den, 1e-15f);
    float s = sqrtf(fmaxf(nsq, 0.0f));
    s = fminf(s, den * 0.9999999f);
    return __logf(__fdividef(den + s, den - s));
}

// Scratch (no allocations allowed)
__device__ float g_c[(size_t)NC * PD];   // corpus projections [row][64]
__device__ float g_cyn[NC];              // tanh^2(||h_lin||)
__device__ float g_q[(size_t)NQ * PD];
__device__ float g_qxn[NQ];
__device__ float g_qw[(size_t)NQ * 3];

// ---------------------------------------------------------------------------
// Kernel 1: weight MLP (unchanged, passing since R5)
// ---------------------------------------------------------------------------
__global__ __launch_bounds__(256) void mlp_kernel(
    const float* __restrict__ xq,
    const float* __restrict__ W1, const float* __restrict__ b1,
    const float* __restrict__ W2, const float* __restrict__ b2)
{
    __shared__ float xs[D];
    __shared__ float hid[32];

    const int q    = blockIdx.x;
    const int tid  = threadIdx.x;
    const int warp = tid >> 5, lane = tid & 31;

    const float4* xrow4 = (const float4*)(xq + (size_t)q * D);
    if (tid < D / 4) ((float4*)xs)[tid] = xrow4[tid];
    __syncthreads();

    float acc0 = 0.f, acc1 = 0.f, acc2 = 0.f, acc3 = 0.f;
    const float* w0  = W1 + (size_t)(warp * 4 + 0) * D;
    const float* w1r = W1 + (size_t)(warp * 4 + 1) * D;
    const float* w2r = W1 + (size_t)(warp * 4 + 2) * D;
    const float* w3r = W1 + (size_t)(warp * 4 + 3) * D;
    #pragma unroll 4
    for (int k = lane; k < D; k += 32) {
        float xv = xs[k];
        acc0 = fmaf(w0[k],  xv, acc0);
        acc1 = fmaf(w1r[k], xv, acc1);
        acc2 = fmaf(w2r[k], xv, acc2);
        acc3 = fmaf(w3r[k], xv, acc3);
    }
    #pragma unroll
    for (int o = 16; o; o >>= 1) {
        acc0 += __shfl_xor_sync(0xffffffffu, acc0, o);
        acc1 += __shfl_xor_sync(0xffffffffu, acc1, o);
        acc2 += __shfl_xor_sync(0xffffffffu, acc2, o);
        acc3 += __shfl_xor_sync(0xffffffffu, acc3, o);
    }
    if (lane == 0) {
        hid[warp * 4 + 0] = fmaxf(acc0 + b1[warp * 4 + 0], 0.0f);
        hid[warp * 4 + 1] = fmaxf(acc1 + b1[warp * 4 + 1], 0.0f);
        hid[warp * 4 + 2] = fmaxf(acc2 + b1[warp * 4 + 2], 0.0f);
        hid[warp * 4 + 3] = fmaxf(acc3 + b1[warp * 4 + 3], 0.0f);
    }
    __syncthreads();

    if (warp == 0) {
        float h = hid[lane];
        #pragma unroll
        for (int i = 0; i < 3; i++) {
            float p = h * W2[i * 32 + lane];
            #pragma unroll
            for (int o = 16; o; o >>= 1) p += __shfl_xor_sync(0xffffffffu, p, o);
            if (lane == 0) {
                float z  = p + b2[i];
                float sp = fmaxf(z, 0.0f) + log1pf(expf(-fabsf(z)));
                g_qw[(size_t)q * 3 + i] = sp;
            }
        }
    }
}

// ---------------------------------------------------------------------------
// Kernel 2: projection GEMM (unchanged from R11-passing version).
// ---------------------------------------------------------------------------
#define BK 32
#define ROWPAD 132
#define NCB128 (NC / 128)
#define NQB128 (NQ / 128)

#define XS_OFF  0
#define WS_OFF  (BK * ROWPAD)
#define OB_SZ   (128 * 68)
#define SRAW_FLOATS (OB_SZ > (BK*ROWPAD + BK*68) ? OB_SZ : (BK*ROWPAD + BK*68))

__global__ __launch_bounds__(256) void proj_kernel(
    const float* __restrict__ xc,
    const float* __restrict__ xq,
    const float* __restrict__ We, const float* __restrict__ be,
    const float* __restrict__ Wh, const float* __restrict__ bh,
    const float* __restrict__ Ws, const float* __restrict__ bs,
    const float* __restrict__ scale_h_p)
{
    __shared__ __align__(16) float sraw[SRAW_FLOATS];
    __shared__ float bias_s[64];

    float* xs  = sraw + XS_OFF;
    float* wsm = sraw + WS_OFF;
    float* ob  = sraw;

    const int tid = threadIdx.x;
    const int blk = blockIdx.x;
    const bool isQ  = (blk >= NCB128);
    const int  row0 = isQ ? (blk - NCB128) * 128 : blk * 128;
    const float* xsrc = isQ ? xq : xc;
    float* gout = isQ ? g_q  : g_c;
    float* gyn  = isQ ? g_qxn : g_cyn;

    if (tid < 64) {
        float b;
        if (tid < 32)      b = be[tid];
        else if (tid < 48) b = bh[tid - 32];
        else               b = bs[tid - 48];
        bias_s[tid] = b;
    }

    const float* wrow_base[2];
    {
        int n0 = (tid + 0 * 256) >> 3;
        int n1 = (tid + 1 * 256) >> 3;
        wrow_base[0] = (n0 < 32) ? We + (size_t)n0 * D
                      : (n0 < 48) ? Wh + (size_t)(n0 - 32) * D
                                  : Ws + (size_t)(n0 - 48) * D;
        wrow_base[1] = (n1 < 32) ? We + (size_t)n1 * D
                      : (n1 < 48) ? Wh + (size_t)(n1 - 32) * D
                                  : Ws + (size_t)(n1 - 48) * D;
    }

    const int tr = (tid >> 4) * 8;
    const int tc = (tid & 15) * 4;

    u64 acc[8][2] = {};
    const float* xbase = xsrc + (size_t)row0 * D;

    for (int kk = 0; kk < D; kk += BK) {
        float4 xv[4], wv[2];
        #pragma unroll
        for (int i = 0; i < 4; i++) {
            int idx = tid + i * 256;
            int r   = idx >> 3;
            int k4  = (idx & 7) * 4;
            xv[i] = *(const float4*)(xbase + (size_t)r * D + kk + k4);
        }
        #pragma unroll
        for (int i = 0; i < 2; i++) {
            int idx = tid + i * 256;
            int k4  = (idx & 7) * 4;
            wv[i] = *(const float4*)(wrow_base[i] + kk + k4);
        }
        __syncthreads();
        #pragma unroll
        for (int i = 0; i < 4; i++) {
            int idx = tid + i * 256;
            int r   = idx >> 3;
            int k4  = (idx & 7) * 4;
            xs[(k4 + 0) * ROWPAD + r] = xv[i].x;
            xs[(k4 + 1) * ROWPAD + r] = xv[i].y;
            xs[(k4 + 2) * ROWPAD + r] = xv[i].z;
            xs[(k4 + 3) * ROWPAD + r] = xv[i].w;
        }
        #pragma unroll
        for (int i = 0; i < 2; i++) {
            int idx = tid + i * 256;
            int n   = idx >> 3;
            int k4  = (idx & 7) * 4;
            wsm[(k4 + 0) * 68 + n] = wv[i].x;
            wsm[(k4 + 1) * 68 + n] = wv[i].y;
            wsm[(k4 + 2) * 68 + n] = wv[i].z;
            wsm[(k4 + 3) * 68 + n] = wv[i].w;
        }
        __syncthreads();

        #pragma unroll
        for (int k = 0; k < BK; k++) {
            float4 a0 = *(const float4*)&xs[k * ROWPAD + tr];
            float4 a1 = *(const float4*)&xs[k * ROWPAD + tr + 4];
            ulonglong2 b = *(const ulonglong2*)&wsm[k * 68 + tc];
            u64 ap[8];
            ap[0] = pack2(a0.x); ap[1] = pack2(a0.y);
            ap[2] = pack2(a0.z); ap[3] = pack2(a0.w);
            ap[4] = pack2(a1.x); ap[5] = pack2(a1.y);
            ap[6] = pack2(a1.z); ap[7] = pack2(a1.w);
            #pragma unroll
            for (int i = 0; i < 8; i++) {
                fma2(acc[i][0], ap[i], b.x);
                fma2(acc[i][1], ap[i], b.y);
            }
        }
        __syncthreads();
    }

    #pragma unroll
    for (int i = 0; i < 8; i++) {
        float v0, v1, v2, v3;
        unpack2(v0, v1, acc[i][0]);
        unpack2(v2, v3, acc[i][1]);
        float4 w4 = {v0, v1, v2, v3};
        *(float4*)&ob[(tr + i) * 68 + tc] = w4;
    }
    __syncthreads();

    const float sc = *scale_h_p;
    #pragma unroll
    for (int it = 0; it < 2; it++) {
        const int r    = (tid >> 2) + it * 64;
        const int part = tid & 3;
        const int cbase = part * 16;
        float vals[16];
        float ss = 0.0f;
        #pragma unroll
        for (int j = 0; j < 16; j++) {
            float v = ob[r * 68 + cbase + j] + bias_s[cbase + j];
            if (part == 2) v *= sc;
            vals[j] = v;
            ss += v * v;
        }
        float other = __shfl_xor_sync(0xffffffffu, ss, 1);
        float seg   = (part < 2) ? (ss + other) : ss;

        const int grow = row0 + r;
        float* orow = gout + (size_t)grow * PD + cbase;
        if (part == 2) {
            float n  = fmaxf(sqrtf(seg), 1e-15f);
            float ex = __expf(2.0f * n);
            float th = 1.0f - 2.0f / (ex + 1.0f);
            float f  = th / n;
            #pragma unroll
            for (int j = 0; j < 16; j++) orow[j] = vals[j] * f;
            gyn[grow] = th * th;
        } else {
            float inv = rsqrtf(seg);
            #pragma unroll
            for (int j = 0; j < 16; j++) orow[j] = vals[j] * inv;
        }
    }
}

// ---------------------------------------------------------------------------
// Kernel 3: pairwise.  64q x 64c tile, 256 threads, 4x4 via f32x2.
// q-tile stored DUPLICATED (qs2[k][2q]=[2q+1]=v) -> a-operands are LDS.64,
// no per-k packing.  Epilogue fully 2-wide except the 4 scalar MUFU ops.
// ---------------------------------------------------------------------------
#define QPITCH2 132   // duplicated q-tile pitch (floats)
#define PW_QS2   0
#define PW_CS    (64 * QPITCH2)                 // cs[64][68]
#define PW_SQXN  (PW_CS + 64 * 68)
#define PW_SQW   (PW_SQXN + 64)
#define PW_SCYN  (PW_SQW + 64 * 3)
#define PW_FLOATS (PW_SCYN + 64)
#define PW_SMEM  (PW_FLOATS * 4)               // bytes

__global__ __launch_bounds__(256) void pairwise_kernel(float* __restrict__ out)
{
    extern __shared__ __align__(16) float psm[];
    float* qs2  = psm + PW_QS2;
    float* cs   = psm + PW_CS;
    float* sqxn = psm + PW_SQXN;
    float* sqw  = psm + PW_SQW;
    float* scyn = psm + PW_SCYN;

    const int tid   = threadIdx.x;
    const int c0blk = blockIdx.x * 64;
    const int q0blk = blockIdx.y * 64;

    #pragma unroll
    for (int i = 0; i < 4; i++) {
        int f4  = tid + i * 256;         // 0..1023
        int row = f4 >> 4;               // 0..63
        int k4  = (f4 & 15) * 4;
        float4 v = *(const float4*)(g_q + (size_t)(q0blk + row) * PD + k4);
        float* q0 = qs2 + (k4 + 0) * QPITCH2 + 2 * row;
        float* q1 = qs2 + (k4 + 1) * QPITCH2 + 2 * row;
        float* q2 = qs2 + (k4 + 2) * QPITCH2 + 2 * row;
        float* q3 = qs2 + (k4 + 3) * QPITCH2 + 2 * row;
        q0[0] = v.x; q0[1] = v.x;
        q1[0] = v.y; q1[1] = v.y;
        q2[0] = v.z; q2[1] = v.z;
        q3[0] = v.w; q3[1] = v.w;
        float4 w = *(const float4*)(g_c + (size_t)(c0blk + row) * PD + k4);
        cs[(k4 + 0) * 68 + row] = w.x;
        cs[(k4 + 1) * 68 + row] = w.y;
        cs[(k4 + 2) * 68 + row] = w.z;
        cs[(k4 + 3) * 68 + row] = w.w;
    }
    if (tid < 64) {
        sqxn[tid]        = g_qxn[q0blk + tid];
        scyn[tid]        = g_cyn[c0blk + tid];
        sqw[tid * 3 + 0] = g_qw[(size_t)(q0blk + tid) * 3 + 0];
        sqw[tid * 3 + 1] = g_qw[(size_t)(q0blk + tid) * 3 + 1];
        sqw[tid * 3 + 2] = g_qw[(size_t)(q0blk + tid) * 3 + 2];
    }
    __syncthreads();

    const int tq0 = (tid >> 4) * 4;
    const int tc0 = (tid & 15) * 4;

    u64 ae[4][2] = {}, ah[4][2] = {}, as2[4][2] = {};

    #pragma unroll
    for (int k = 0; k < 32; k++) {
        const float* qk = qs2 + k * QPITCH2 + 2 * tq0;
        u64 a0 = *(const u64*)(qk + 0), a1 = *(const u64*)(qk + 2);
        u64 a2 = *(const u64*)(qk + 4), a3 = *(const u64*)(qk + 6);
        ulonglong2 b = *(const ulonglong2*)&cs[k * 68 + tc0];
        fma2(ae[0][0], a0, b.x); fma2(ae[0][1], a0, b.y);
        fma2(ae[1][0], a1, b.x); fma2(ae[1][1], a1, b.y);
        fma2(ae[2][0], a2, b.x); fma2(ae[2][1], a2, b.y);
        fma2(ae[3][0], a3, b.x); fma2(ae[3][1], a3, b.y);
    }
    #pragma unroll
    for (int k = 32; k < 48; k++) {
        const float* qk = qs2 + k * QPITCH2 + 2 * tq0;
        u64 a0 = *(const u64*)(qk + 0), a1 = *(const u64*)(qk + 2);
        u64 a2 = *(const u64*)(qk + 4), a3 = *(const u64*)(qk + 6);
        ulonglong2 b = *(const ulonglong2*)&cs[k * 68 + tc0];
        fma2(ah[0][0], a0, b.x); fma2(ah[0][1], a0, b.y);
        fma2(ah[1][0], a1, b.x); fma2(ah[1][1], a1, b.y);
        fma2(ah[2][0], a2, b.x); fma2(ah[2][1], a2, b.y);
        fma2(ah[3][0], a3, b.x); fma2(ah[3][1], a3, b.y);
    }
    #pragma unroll
    for (int k = 48; k < 64; k++) {
        const float* qk = qs2 + k * QPITCH2 + 2 * tq0;
        u64 a0 = *(const u64*)(qk + 0), a1 = *(const u64*)(qk + 2);
        u64 a2 = *(const u64*)(qk + 4), a3 = *(const u64*)(qk + 6);
        ulonglong2 b = *(const ulonglong2*)&cs[k * 68 + tc0];
        fma2(as2[0][0], a0, b.x); fma2(as2[0][1], a0, b.y);
        fma2(as2[1][0], a1, b.x); fma2(as2[1][1], a1, b.y);
        fma2(as2[2][0], a2, b.x); fma2(as2[2][1], a2, b.y);
        fma2(as2[3][0], a3, b.x); fma2(as2[3][1], a3, b.y);
    }

    // ---- epilogue: 2-wide over col pairs (accumulators already paired) ----
    const u64 c_m2 = pack2(-2.0f);
    const u64 c_2  = pack2(2.0f);
    const u64 c_1  = pack2(1.0f);
    const u64 P0 = pack2(-0.0012624911f), P1 = pack2(0.0066700901f);
    const u64 P2 = pack2(-0.0170881256f), P3 = pack2(0.0308918810f);
    const u64 P4 = pack2(-0.0501743046f), P5 = pack2(0.0889789874f);
    const u64 P6 = pack2(-0.2145988016f), P7 = pack2(1.5707963050f);

    u64 yn2[2], A2[2];
    yn2[0] = *(const u64*)&scyn[tc0];
    yn2[1] = *(const u64*)&scyn[tc0 + 2];
    A2[0]  = fma2v(yn2[0], c_1, c_1);       // 1 + yn
    A2[1]  = fma2v(yn2[1], c_1, c_1);

    #pragma unroll
    for (int i = 0; i < 4; i++) {
        const int q = tq0 + i;
        const float xn = sqxn[q];
        const float beta = 1.0f - xn;
        const u64 xn2  = pack2(xn);
        const u64 m2b  = pack2(-2.0f * beta);
        const u64 bb   = pack2(beta * beta);
        const u64 w0n  = pack2(-sqw[q * 3 + 0]);
        const u64 w1n  = pack2(-sqw[q * 3 + 1]);
        const u64 w2n  = pack2(-sqw[q * 3 + 2]);
        u64 rv[2];
        #pragma unroll
        for (int jp = 0; jp < 2; jp++) {
            const u64 ev2 = ae[i][jp], dt2 = ah[i][jp], sv2 = as2[i][jp];
            // euclidean: 2 - 2e
            u64 de2 = fma2v(ev2, c_m2, c_2);
            // hyperbolic chain (2-wide FMA)
            u64 xy2    = fma2v(xn2, yn2[jp], c_1);     // 1 + xn*yn
            u64 alpha2 = fma2v(dt2, c_m2, A2[jp]);     // 1 - 2dt + yn
            u64 den2   = fma2v(dt2, c_m2, xy2);        // 1 - 2dt + xn*yn
            u64 t1     = mul2(alpha2, xn2);
            u64 nsq2   = mul2(t1, alpha2);             // alpha^2*xn
            u64 t2     = mul2(alpha2, dt2);
            nsq2 = fma2v(t2, m2b, nsq2);               // - 2*alpha*beta*dt
            nsq2 = fma2v(yn2[jp], bb, nsq2);           // + beta^2*yn
            float n0, n1, d0, d1;
            unpack2(n0, n1, nsq2);
            unpack2(d0, d1, den2);
            float dd0 = hyp_dd(n0, d0);
            float dd1 = hyp_dd(n1, d1);
            u64 ddp = packpair(dd0, dd1);
            u64 dh2 = mul2(ddp, ddp);
            // spherical: clamp scalar, poly 2-wide
            float s0, s1;
            unpack2(s0, s1, sv2);
            s0 = fminf(fmaxf(s0, -0.9999999f), 0.9999999f);
            s1 = fminf(fmaxf(s1, -0.9999999f), 0.9999999f);
            u64 sp  = packpair(s0, s1);
            u64 ax2 = sp & 0x7FFFFFFF7FFFFFFFULL;      // |dots| 2-wide
            u64 p2 = fma2v(ax2, P0, P1);
            p2 = fma2v(p2, ax2, P2);
            p2 = fma2v(p2, ax2, P3);
            p2 = fma2v(p2, ax2, P4);
            p2 = fma2v(p2, ax2, P5);
            p2 = fma2v(p2, ax2, P6);
            p2 = fma2v(p2, ax2, P7);
            float p0, p1v;
            unpack2(p0, p1v, p2);
            float r0 = sqrtf(1.0f - fabsf(s0)) * p0;
            float r1 = sqrtf(1.0f - fabsf(s1)) * p1v;
            float acs0 = (s0 >= 0.0f) ? r0 : 3.14159265358979f - r0;
            float acs1 = (s1 >= 0.0f) ? r1 : 3.14159265358979f - r1;
            u64 acp  = packpair(acs0, acs1);
            u64 ds2v = mul2(acp, acp);
            // combine (weights pre-negated)
            u64 r2 = mul2(de2, w0n);
            r2 = fma2v(dh2, w1n, r2);
            r2 = fma2v(ds2v, w2n, r2);
            rv[jp] = r2;
        }
        float4 res;
        unpack2(res.x, res.y, rv[0]);
        unpack2(res.z, res.w, rv[1]);
        *(float4*)(out + (size_t)(q0blk + q) * NC + c0blk + tc0) = res;
    }
}

// ---------------------------------------------------------------------------
extern "C" void kernel_launch(void* const* d_in, const int* in_sizes, int n_in,
                              void* d_out, int out_size)
{
    const float* xq  = (const float*)d_in[0];
    const float* xc  = (const float*)d_in[1];
    const float* We  = (const float*)d_in[2];
    const float* be  = (const float*)d_in[3];
    const float* Wh  = (const float*)d_in[4];
    const float* bh  = (const float*)d_in[5];
    const float* Ws  = (const float*)d_in[6];
    const float* bs  = (const float*)d_in[7];
    const float* sh  = (const float*)d_in[8];
    const float* W1  = (const float*)d_in[9];
    const float* b1  = (const float*)d_in[10];
    const float* W2  = (const float*)d_in[11];
    const float* b2  = (const float*)d_in[12];
    float* out = (float*)d_out;

    // Unconditional, idempotent (no static guards allowed).
    cudaFuncSetAttribute(pairwise_kernel,
                         cudaFuncAttributeMaxDynamicSharedMemorySize, PW_SMEM);

    mlp_kernel<<<NQ, 256>>>(xq, W1, b1, W2, b2);
    proj_kernel<<<NCB128 + NQB128, 256>>>(xc, xq, We, be, Wh, bh, Ws, bs, sh);
    pairwise_kernel<<<dim3(NC / 64, NQ / 64), 256, PW_SMEM>>>(out);
}

// round 15
// speedup vs baseline: 1.2709x; 1.1855x over previous
#include <cuda_runtime.h>
#include <math.h>
#include <stdint.h>

// Problem constants
#define NQ 512
#define NC 65536
#define D  768
#define PD 64          // packed projection dim: e[0:32) h[32:48) s[48:64)

typedef unsigned long long u64;

// packed-fp32 helpers (sm_103 f32x2 — 2x FFMA throughput, exact fp32)
__device__ __forceinline__ u64 pack2(float v) {
    u64 r;
    asm("mov.b64 %0, {%1, %1};" : "=l"(r) : "f"(v));
    return r;
}
__device__ __forceinline__ void fma2(u64& d, u64 a, u64 b) {
    asm("fma.rn.f32x2 %0, %1, %2, %0;" : "+l"(d) : "l"(a), "l"(b));
}
__device__ __forceinline__ void unpack2(float& lo, float& hi, u64 v) {
    asm("mov.b64 {%0, %1}, %2;" : "=f"(lo), "=f"(hi) : "l"(v));
}

// fast acos: A&S 4.4.46-style 8-coeff, abs err ~2e-8, branch-free
__device__ __forceinline__ float facos(float x) {
    float ax = fabsf(x);
    float p = fmaf(ax, -0.0012624911f, 0.0066700901f);
    p = fmaf(p, ax, -0.0170881256f);
    p = fmaf(p, ax,  0.0308918810f);
    p = fmaf(p, ax, -0.0501743046f);
    p = fmaf(p, ax,  0.0889789874f);
    p = fmaf(p, ax, -0.2145988016f);
    p = fmaf(p, ax,  1.5707963050f);
    float r = sqrtf(1.0f - ax) * p;
    return (x >= 0.0f) ? r : (3.14159265358979f - r);
}

// hyperbolic: dd = 2*atanh(clamp(sqrt(nsq)/den, 0, 1-1e-7))
//           = ln((den+s)/(den-s)), s clamped — single divide
__device__ __forceinline__ float hyp_dd(float nsq, float den) {
    den = fmaxf(den, 1e-15f);
    float s = sqrtf(fmaxf(nsq, 0.0f));
    s = fminf(s, den * 0.9999999f);
    return __logf(__fdividef(den + s, den - s));
}

// Scratch (no allocations allowed)
__device__ float g_c[(size_t)NC * PD];   // corpus projections [row][64]
__device__ float g_cyn[NC];              // tanh^2(||h_lin||)
__device__ float g_q[(size_t)NQ * PD];
__device__ float g_qxn[NQ];
__device__ float g_qw[(size_t)NQ * 3];

// ---------------------------------------------------------------------------
// Kernel 1: weight MLP (unchanged, passing since R5)
// ---------------------------------------------------------------------------
__global__ __launch_bounds__(256) void mlp_kernel(
    const float* __restrict__ xq,
    const float* __restrict__ W1, const float* __restrict__ b1,
    const float* __restrict__ W2, const float* __restrict__ b2)
{
    __shared__ float xs[D];
    __shared__ float hid[32];

    const int q    = blockIdx.x;
    const int tid  = threadIdx.x;
    const int warp = tid >> 5, lane = tid & 31;

    const float4* xrow4 = (const float4*)(xq + (size_t)q * D);
    if (tid < D / 4) ((float4*)xs)[tid] = xrow4[tid];
    __syncthreads();

    float acc0 = 0.f, acc1 = 0.f, acc2 = 0.f, acc3 = 0.f;
    const float* w0  = W1 + (size_t)(warp * 4 + 0) * D;
    const float* w1r = W1 + (size_t)(warp * 4 + 1) * D;
    const float* w2r = W1 + (size_t)(warp * 4 + 2) * D;
    const float* w3r = W1 + (size_t)(warp * 4 + 3) * D;
    #pragma unroll 4
    for (int k = lane; k < D; k += 32) {
        float xv = xs[k];
        acc0 = fmaf(w0[k],  xv, acc0);
        acc1 = fmaf(w1r[k], xv, acc1);
        acc2 = fmaf(w2r[k], xv, acc2);
        acc3 = fmaf(w3r[k], xv, acc3);
    }
    #pragma unroll
    for (int o = 16; o; o >>= 1) {
        acc0 += __shfl_xor_sync(0xffffffffu, acc0, o);
        acc1 += __shfl_xor_sync(0xffffffffu, acc1, o);
        acc2 += __shfl_xor_sync(0xffffffffu, acc2, o);
        acc3 += __shfl_xor_sync(0xffffffffu, acc3, o);
    }
    if (lane == 0) {
        hid[warp * 4 + 0] = fmaxf(acc0 + b1[warp * 4 + 0], 0.0f);
        hid[warp * 4 + 1] = fmaxf(acc1 + b1[warp * 4 + 1], 0.0f);
        hid[warp * 4 + 2] = fmaxf(acc2 + b1[warp * 4 + 2], 0.0f);
        hid[warp * 4 + 3] = fmaxf(acc3 + b1[warp * 4 + 3], 0.0f);
    }
    __syncthreads();

    if (warp == 0) {
        float h = hid[lane];
        #pragma unroll
        for (int i = 0; i < 3; i++) {
            float p = h * W2[i * 32 + lane];
            #pragma unroll
            for (int o = 16; o; o >>= 1) p += __shfl_xor_sync(0xffffffffu, p, o);
            if (lane == 0) {
                float z  = p + b2[i];
                float sp = fmaxf(z, 0.0f) + log1pf(expf(-fabsf(z)));
                g_qw[(size_t)q * 3 + i] = sp;
            }
        }
    }
}

// ---------------------------------------------------------------------------
// Kernel 2: projection GEMM (unchanged from R11-passing version).
// ---------------------------------------------------------------------------
#define BK 32
#define ROWPAD 132
#define NCB128 (NC / 128)
#define NQB128 (NQ / 128)

#define XS_OFF  0
#define WS_OFF  (BK * ROWPAD)
#define OB_SZ   (128 * 68)
#define SRAW_FLOATS (OB_SZ > (BK*ROWPAD + BK*68) ? OB_SZ : (BK*ROWPAD + BK*68))

__global__ __launch_bounds__(256) void proj_kernel(
    const float* __restrict__ xc,
    const float* __restrict__ xq,
    const float* __restrict__ We, const float* __restrict__ be,
    const float* __restrict__ Wh, const float* __restrict__ bh,
    const float* __restrict__ Ws, const float* __restrict__ bs,
    const float* __restrict__ scale_h_p)
{
    __shared__ __align__(16) float sraw[SRAW_FLOATS];
    __shared__ float bias_s[64];

    float* xs  = sraw + XS_OFF;
    float* wsm = sraw + WS_OFF;
    float* ob  = sraw;

    const int tid = threadIdx.x;
    const int blk = blockIdx.x;
    const bool isQ  = (blk >= NCB128);
    const int  row0 = isQ ? (blk - NCB128) * 128 : blk * 128;
    const float* xsrc = isQ ? xq : xc;
    float* gout = isQ ? g_q  : g_c;
    float* gyn  = isQ ? g_qxn : g_cyn;

    if (tid < 64) {
        float b;
        if (tid < 32)      b = be[tid];
        else if (tid < 48) b = bh[tid - 32];
        else               b = bs[tid - 48];
        bias_s[tid] = b;
    }

    const float* wrow_base[2];
    {
        int n0 = (tid + 0 * 256) >> 3;
        int n1 = (tid + 1 * 256) >> 3;
        wrow_base[0] = (n0 < 32) ? We + (size_t)n0 * D
                      : (n0 < 48) ? Wh + (size_t)(n0 - 32) * D
                                  : Ws + (size_t)(n0 - 48) * D;
        wrow_base[1] = (n1 < 32) ? We + (size_t)n1 * D
                      : (n1 < 48) ? Wh + (size_t)(n1 - 32) * D
                                  : Ws + (size_t)(n1 - 48) * D;
    }

    const int tr = (tid >> 4) * 8;
    const int tc = (tid & 15) * 4;

    u64 acc[8][2] = {};
    const float* xbase = xsrc + (size_t)row0 * D;

    for (int kk = 0; kk < D; kk += BK) {
        float4 xv[4], wv[2];
        #pragma unroll
        for (int i = 0; i < 4; i++) {
            int idx = tid + i * 256;
            int r   = idx >> 3;
            int k4  = (idx & 7) * 4;
            xv[i] = *(const float4*)(xbase + (size_t)r * D + kk + k4);
        }
        #pragma unroll
        for (int i = 0; i < 2; i++) {
            int idx = tid + i * 256;
            int k4  = (idx & 7) * 4;
            wv[i] = *(const float4*)(wrow_base[i] + kk + k4);
        }
        __syncthreads();
        #pragma unroll
        for (int i = 0; i < 4; i++) {
            int idx = tid + i * 256;
            int r   = idx >> 3;
            int k4  = (idx & 7) * 4;
            xs[(k4 + 0) * ROWPAD + r] = xv[i].x;
            xs[(k4 + 1) * ROWPAD + r] = xv[i].y;
            xs[(k4 + 2) * ROWPAD + r] = xv[i].z;
            xs[(k4 + 3) * ROWPAD + r] = xv[i].w;
        }
        #pragma unroll
        for (int i = 0; i < 2; i++) {
            int idx = tid + i * 256;
            int n   = idx >> 3;
            int k4  = (idx & 7) * 4;
            wsm[(k4 + 0) * 68 + n] = wv[i].x;
            wsm[(k4 + 1) * 68 + n] = wv[i].y;
            wsm[(k4 + 2) * 68 + n] = wv[i].z;
            wsm[(k4 + 3) * 68 + n] = wv[i].w;
        }
        __syncthreads();

        #pragma unroll
        for (int k = 0; k < BK; k++) {
            float4 a0 = *(const float4*)&xs[k * ROWPAD + tr];
            float4 a1 = *(const float4*)&xs[k * ROWPAD + tr + 4];
            ulonglong2 b = *(const ulonglong2*)&wsm[k * 68 + tc];
            u64 ap[8];
            ap[0] = pack2(a0.x); ap[1] = pack2(a0.y);
            ap[2] = pack2(a0.z); ap[3] = pack2(a0.w);
            ap[4] = pack2(a1.x); ap[5] = pack2(a1.y);
            ap[6] = pack2(a1.z); ap[7] = pack2(a1.w);
            #pragma unroll
            for (int i = 0; i < 8; i++) {
                fma2(acc[i][0], ap[i], b.x);
                fma2(acc[i][1], ap[i], b.y);
            }
        }
        __syncthreads();
    }

    #pragma unroll
    for (int i = 0; i < 8; i++) {
        float v0, v1, v2, v3;
        unpack2(v0, v1, acc[i][0]);
        unpack2(v2, v3, acc[i][1]);
        float4 w4 = {v0, v1, v2, v3};
        *(float4*)&ob[(tr + i) * 68 + tc] = w4;
    }
    __syncthreads();

    const float sc = *scale_h_p;
    #pragma unroll
    for (int it = 0; it < 2; it++) {
        const int r    = (tid >> 2) + it * 64;
        const int part = tid & 3;
        const int cbase = part * 16;
        float vals[16];
        float ss = 0.0f;
        #pragma unroll
        for (int j = 0; j < 16; j++) {
            float v = ob[r * 68 + cbase + j] + bias_s[cbase + j];
            if (part == 2) v *= sc;
            vals[j] = v;
            ss += v * v;
        }
        float other = __shfl_xor_sync(0xffffffffu, ss, 1);
        float seg   = (part < 2) ? (ss + other) : ss;

        const int grow = row0 + r;
        float* orow = gout + (size_t)grow * PD + cbase;
        if (part == 2) {
            float n  = fmaxf(sqrtf(seg), 1e-15f);
            float ex = __expf(2.0f * n);
            float th = 1.0f - 2.0f / (ex + 1.0f);
            float f  = th / n;
            #pragma unroll
            for (int j = 0; j < 16; j++) orow[j] = vals[j] * f;
            gyn[grow] = th * th;
        } else {
            float inv = rsqrtf(seg);
            #pragma unroll
            for (int j = 0; j < 16; j++) orow[j] = vals[j] * inv;
        }
    }
}

// ---------------------------------------------------------------------------
// Kernel 3: pairwise — R5 structure exactly (layout/accumulators/occupancy),
// epilogue scalar math tightened: facos poly, 1-divide hyperbolic, folded de.
// ---------------------------------------------------------------------------
__global__ __launch_bounds__(256) void pairwise_kernel(float* __restrict__ out)
{
    __shared__ __align__(16) float qs[64][68];
    __shared__ __align__(16) float cs[64][68];
    __shared__ float sqxn[64];
    __shared__ float sqw[64][3];
    __shared__ float scyn[64];

    const int tid   = threadIdx.x;
    const int c0blk = blockIdx.x * 64;
    const int q0blk = blockIdx.y * 64;

    #pragma unroll
    for (int i = 0; i < 4; i++) {
        int f4  = tid + i * 256;
        int row = f4 >> 4;
        int k4  = (f4 & 15) * 4;
        float4 v = *(const float4*)(g_q + (size_t)(q0blk + row) * PD + k4);
        qs[k4+0][row] = v.x; qs[k4+1][row] = v.y;
        qs[k4+2][row] = v.z; qs[k4+3][row] = v.w;
        float4 w = *(const float4*)(g_c + (size_t)(c0blk + row) * PD + k4);
        cs[k4+0][row] = w.x; cs[k4+1][row] = w.y;
        cs[k4+2][row] = w.z; cs[k4+3][row] = w.w;
    }
    if (tid < 64) {
        sqxn[tid]   = g_qxn[q0blk + tid];
        scyn[tid]   = g_cyn[c0blk + tid];
        sqw[tid][0] = g_qw[(size_t)(q0blk + tid) * 3 + 0];
        sqw[tid][1] = g_qw[(size_t)(q0blk + tid) * 3 + 1];
        sqw[tid][2] = g_qw[(size_t)(q0blk + tid) * 3 + 2];
    }
    __syncthreads();

    const int tq0 = (tid >> 4) * 4;
    const int tc0 = (tid & 15) * 4;

    u64 ae[4][2] = {}, ah[4][2] = {}, as2[4][2] = {};

    #pragma unroll
    for (int k = 0; k < 32; k++) {
        float4 a = *(const float4*)&qs[k][tq0];
        ulonglong2 b = *(const ulonglong2*)&cs[k][tc0];
        u64 ap0 = pack2(a.x), ap1 = pack2(a.y),
            ap2 = pack2(a.z), ap3 = pack2(a.w);
        fma2(ae[0][0], ap0, b.x); fma2(ae[0][1], ap0, b.y);
        fma2(ae[1][0], ap1, b.x); fma2(ae[1][1], ap1, b.y);
        fma2(ae[2][0], ap2, b.x); fma2(ae[2][1], ap2, b.y);
        fma2(ae[3][0], ap3, b.x); fma2(ae[3][1], ap3, b.y);
    }
    #pragma unroll
    for (int k = 32; k < 48; k++) {
        float4 a = *(const float4*)&qs[k][tq0];
        ulonglong2 b = *(const ulonglong2*)&cs[k][tc0];
        u64 ap0 = pack2(a.x), ap1 = pack2(a.y),
            ap2 = pack2(a.z), ap3 = pack2(a.w);
        fma2(ah[0][0], ap0, b.x); fma2(ah[0][1], ap0, b.y);
        fma2(ah[1][0], ap1, b.x); fma2(ah[1][1], ap1, b.y);
        fma2(ah[2][0], ap2, b.x); fma2(ah[2][1], ap2, b.y);
        fma2(ah[3][0], ap3, b.x); fma2(ah[3][1], ap3, b.y);
    }
    #pragma unroll
    for (int k = 48; k < 64; k++) {
        float4 a = *(const float4*)&qs[k][tq0];
        ulonglong2 b = *(const ulonglong2*)&cs[k][tc0];
        u64 ap0 = pack2(a.x), ap1 = pack2(a.y),
            ap2 = pack2(a.z), ap3 = pack2(a.w);
        fma2(as2[0][0], ap0, b.x); fma2(as2[0][1], ap0, b.y);
        fma2(as2[1][0], ap1, b.x); fma2(as2[1][1], ap1, b.y);
        fma2(as2[2][0], ap2, b.x); fma2(as2[2][1], ap2, b.y);
        fma2(as2[3][0], ap3, b.x); fma2(as2[3][1], ap3, b.y);
    }

    #pragma unroll
    for (int i = 0; i < 4; i++) {
        const int q    = tq0 + i;
        const float xn = sqxn[q];
        const float w0 = sqw[q][0], w1 = sqw[q][1], w2 = sqw[q][2];
        const float beta = 1.0f - xn;
        const float tw0  = 2.0f * w0;   // folded euclidean: w0*(2-2e) = tw0 - tw0*e

        float ev[4], hv[4], sv[4];
        unpack2(ev[0], ev[1], ae[i][0]);  unpack2(ev[2], ev[3], ae[i][1]);
        unpack2(hv[0], hv[1], ah[i][0]);  unpack2(hv[2], hv[3], ah[i][1]);
        unpack2(sv[0], sv[1], as2[i][0]); unpack2(sv[2], sv[3], as2[i][1]);

        float rv[4];
        #pragma unroll
        for (int j = 0; j < 4; j++) {
            const float yn = scyn[tc0 + j];
            // spherical: clamp + poly acos
            float dots = fminf(fmaxf(sv[j], -0.9999999f), 0.9999999f);
            float acs  = facos(dots);
            float ds   = acs * acs;
            // hyperbolic: single-divide log form
            float dt    = hv[j];
            float alpha = 1.0f - 2.0f * dt + yn;
            float nsq   = alpha*alpha*xn - 2.0f*alpha*beta*dt + beta*beta*yn;
            float den   = 1.0f - 2.0f*dt + xn*yn;
            float dd    = hyp_dd(nsq, den);
            float dh    = dd * dd;
            // combine: -(tw0 - tw0*e + w1*dh + w2*ds)
            float acc = fmaf(w1, dh, fmaf(w2, ds, tw0));
            rv[j] = fmaf(tw0, ev[j], -acc);
        }
        float4 res = {rv[0], rv[1], rv[2], rv[3]};
        *(float4*)(out + (size_t)(q0blk + q) * NC + c0blk + tc0) = res;
    }
}

// ---------------------------------------------------------------------------
extern "C" void kernel_launch(void* const* d_in, const int* in_sizes, int n_in,
                              void* d_out, int out_size)
{
    const float* xq  = (const float*)d_in[0];
    const float* xc  = (const float*)d_in[1];
    const float* We  = (const float*)d_in[2];
    const float* be  = (const float*)d_in[3];
    const float* Wh  = (const float*)d_in[4];
    const float* bh  = (const float*)d_in[5];
    const float* Ws  = (const float*)d_in[6];
    const float* bs  = (const float*)d_in[7];
    const float* sh  = (const float*)d_in[8];
    const float* W1  = (const float*)d_in[9];
    const float* b1  = (const float*)d_in[10];
    const float* W2  = (const float*)d_in[11];
    const float* b2  = (const float*)d_in[12];
    float* out = (float*)d_out;

    mlp_kernel<<<NQ, 256>>>(xq, W1, b1, W2, b2);
    proj_kernel<<<NCB128 + NQB128, 256>>>(xc, xq, We, be, Wh, bh, Ws, bs, sh);
    pairwise_kernel<<<dim3(NC / 64, NQ / 64), 256>>>(out);
}